// round 11
// baseline (speedup 1.0000x reference)
#include <cuda_runtime.h>
#include <cuda_fp16.h>
#include <cstdint>

#define N_NODES   200000
#define N_EDGES   400000
#define IN_CH     768
#define HID_CH    256
#define NUM_GRAPHS 8000

// ---------------- scratch (device globals: no allocations allowed) ----------
__device__ int   g_is64;
__device__ int   g_total;
__device__ int   g_edges[2 * N_EDGES];          // [src(E), dst(E)] as int32
__device__ int   g_batch[N_NODES];
__device__ int   g_indeg[N_NODES];
__device__ int   g_rowbeg[N_NODES];             // CSR range start (arbitrary order)
__device__ int   g_cursor[N_NODES];
__device__ int   g_csrc[N_EDGES];               // CSR-by-dst: src ids
__device__ float g_dinv[N_NODES];               // rsqrt(1 + indeg)
__device__ __half2 g_h[(size_t)N_NODES * 128];  // GEMM output, fp16 (gather-read)
__device__ __half2 g_a16[(size_t)(N_NODES + 128) * 128]; // relu(agg+b1), fp16 (padded tail)
__device__ float g_a[(size_t)N_NODES * 256];    // layer-2 agg output, fp32 (pool input)
__device__ __half g_w1[256 * IN_CH];            // W^T fp16, [n][k] K-major
__device__ __half g_w2[256 * HID_CH];

// ---------------- setup ------------------------------------------------------
__global__ void k_detect(const int* ei32) {
    __shared__ int any;
    if (threadIdx.x == 0) any = 0;
    __syncthreads();
    int idx = threadIdx.x * 3120 + 1;           // max 795601 < 800000 (safe if int32)
    if (ei32[idx] != 0) any = 1;
    __syncthreads();
    if (threadIdx.x == 0) { g_is64 = (any == 0) ? 1 : 0; g_total = 0; }
}

__global__ void k_wprep(const float* __restrict__ W1, const float* __restrict__ W2) {
    int i = blockIdx.x * blockDim.x + threadIdx.x;
    if (i < N_NODES) g_indeg[i] = 0;
    if (i < IN_CH * 256) {
        int k = i / 256, n = i % 256;
        g_w1[(size_t)n * IN_CH + k] = __float2half_rn(W1[i]);
    } else {
        int j = i - IN_CH * 256;
        if (j < HID_CH * 256) {
            int k = j / 256, n = j % 256;
            g_w2[(size_t)n * HID_CH + k] = __float2half_rn(W2[j]);
        }
    }
}

__global__ void k_convert_deg(const void* ei, const void* bat) {
    int i = blockIdx.x * blockDim.x + threadIdx.x;
    bool is64 = (g_is64 != 0);
    if (i < N_NODES) {
        g_batch[i] = is64 ? (int)((const long long*)bat)[i] : ((const int*)bat)[i];
    }
    if (i < 2 * N_EDGES) {
        int v = is64 ? (int)((const long long*)ei)[i] : ((const int*)ei)[i];
        g_edges[i] = v;
        if (i >= N_EDGES) atomicAdd(&g_indeg[v], 1);   // dst half
    }
}

__global__ void k_alloc() {
    int i = blockIdx.x * blockDim.x + threadIdx.x;
    if (i >= N_NODES) return;
    int d = g_indeg[i];
    int beg = atomicAdd(&g_total, d);           // uniform-addr -> REDUX aggregated
    g_rowbeg[i] = beg;
    g_cursor[i] = beg;
    g_dinv[i] = rsqrtf(1.0f + (float)d);
}

__global__ void k_fill() {
    int e = blockIdx.x * blockDim.x + threadIdx.x;
    if (e < N_EDGES) {
        int s = g_edges[e], d = g_edges[N_EDGES + e];
        int pos = atomicAdd(&g_cursor[d], 1);
        g_csrc[pos] = s;
    }
}

// ---------------- GEMM helpers ------------------------------------------------
__device__ __forceinline__ void ldsm4(uint32_t r[4], uint32_t addr) {
    asm volatile("ldmatrix.sync.aligned.m8n8.x4.shared.b16 {%0,%1,%2,%3}, [%4];"
        : "=r"(r[0]), "=r"(r[1]), "=r"(r[2]), "=r"(r[3]) : "r"(addr));
}
__device__ __forceinline__ void mma16816(float c[4], const uint32_t a[4], const uint32_t b[2]) {
    asm volatile(
        "mma.sync.aligned.m16n8k16.row.col.f32.f16.f16.f32 "
        "{%0,%1,%2,%3}, {%4,%5,%6,%7}, {%8,%9}, {%0,%1,%2,%3};"
        : "+f"(c[0]), "+f"(c[1]), "+f"(c[2]), "+f"(c[3])
        : "r"(a[0]), "r"(a[1]), "r"(a[2]), "r"(a[3]), "r"(b[0]), "r"(b[1]));
}
__device__ __forceinline__ void cpasync16(uint32_t dst, const void* src) {
    asm volatile("cp.async.cg.shared.global [%0], [%1], 16;" :: "r"(dst), "l"(src));
}
__device__ __forceinline__ uint32_t smem_u32(const void* p) {
    uint32_t a;
    asm("{ .reg .u64 t; cvta.to.shared.u64 t, %1; cvt.u32.u64 %0, t; }" : "=r"(a) : "l"(p));
    return a;
}

// BM=128, BN=128, BK=32. 128 threads = 4 warps (2M x 2N), warp tile 64x64.
// 3-stage cp.async, 2 CTAs/SM. smem/mma = 128 B (vs 192 at 32x64 tiles).
// AHALF: A is fp16 (g_a16), loaded via cp.async (relu+bias pre-applied by agg).
#define BKP 40                       // padded BK row (fp16): 80B stride
#define OFF_B (128 * BKP * 2)        // 10240
#define ST_BYTES (2 * 128 * BKP * 2) // 20480 per stage
#define N_STAGE 3
#define SMEM_DYN (N_STAGE * ST_BYTES) // 61440 (2 CTAs = 123KB <= 228KB)

template<int K, bool AHALF>
__global__ __launch_bounds__(128, 2) void k_gemm_tc(
    const void* __restrict__ Av, const __half* __restrict__ B,
    __half2* __restrict__ H, int M)
{
    extern __shared__ __align__(16) char smem[];
    const uint32_t sb = smem_u32(smem);

    const int tid  = threadIdx.x;
    const int lane = tid & 31;
    const int wid  = tid >> 5;
    const int bn   = blockIdx.x * 128;
    const int bm   = blockIdx.y * 128;
    const int wm   = (wid & 1) * 64;
    const int wn   = (wid >> 1) * 64;

    // loaders: one thread per tile row (0..127)
    const int row = tid;
    const bool aValid = (bm + row) < M;
    const float*  Apf = (const float*) Av + (size_t)(bm + row) * K;
    const __half* Aph = (const __half*)Av + (size_t)(bm + row) * K;  // padded global
    const __half* Bp  = B + (size_t)(bn + row) * K;
    const uint32_t rowOff = (uint32_t)row * (BKP * 2);

    // ldmatrix per-lane addresses
    const uint32_t aOff = (uint32_t)(wm + (lane & 15)) * (BKP * 2) + ((lane >> 4) << 4);
    const uint32_t bOff = (uint32_t)(wn + (lane & 7) + ((lane >> 4) & 1) * 8) * (BKP * 2)
                        + (((lane >> 3) & 1) << 4);

    float acc[4][8][4];
    #pragma unroll
    for (int mt = 0; mt < 4; mt++)
        #pragma unroll
        for (int nt = 0; nt < 8; nt++)
            #pragma unroll
            for (int j = 0; j < 4; j++) acc[mt][nt][j] = 0.0f;

    constexpr int KT = K / 32;

    float4 aReg[8];                        // !AHALF path only (32 floats/row-chunk)
    auto loadA = [&](int kt) {
        #pragma unroll
        for (int i = 0; i < 8; i++)
            aReg[i] = aValid ? *(const float4*)(Apf + kt * 32 + 4 * i)
                             : make_float4(0.f, 0.f, 0.f, 0.f);
    };
    auto stsA = [&](uint32_t stage) {
        uint32_t hw[16];
        #pragma unroll
        for (int i = 0; i < 8; i++) {
            float4 v = aReg[i];
            __half2 h0; h0.x = __float2half_rn(v.x); h0.y = __float2half_rn(v.y);
            __half2 h1; h1.x = __float2half_rn(v.z); h1.y = __float2half_rn(v.w);
            hw[2 * i]     = *(uint32_t*)&h0;
            hw[2 * i + 1] = *(uint32_t*)&h1;
        }
        #pragma unroll
        for (int i = 0; i < 4; i++)
            asm volatile("st.shared.v4.b32 [%0], {%1,%2,%3,%4};"
                :: "r"(stage + rowOff + i * 16),
                   "r"(hw[4*i]), "r"(hw[4*i+1]), "r"(hw[4*i+2]), "r"(hw[4*i+3]) : "memory");
    };
    auto cpA = [&](int kt, uint32_t stage) {   // AHALF path (padded global, no guard)
        #pragma unroll
        for (int u = 0; u < 4; u++)
            cpasync16(stage + rowOff + u * 16, Aph + kt * 32 + u * 8);
    };
    auto cpB = [&](int kt, uint32_t stage) {   // commits the stage's async group
        #pragma unroll
        for (int u = 0; u < 4; u++)
            cpasync16(stage + OFF_B + rowOff + u * 16, Bp + kt * 32 + u * 8);
        asm volatile("cp.async.commit_group;" ::: "memory");
    };
    auto fillStage = [&](int kt, uint32_t stage) {
        if constexpr (AHALF) { cpA(kt, stage); }
        else                 { loadA(kt); stsA(stage); }
        cpB(kt, stage);
    };

    // prologue: stages 0 and 1
    fillStage(0, sb);
    fillStage(1, sb + ST_BYTES);

    for (int kt = 0; kt < KT; kt++) {
        const uint32_t cur = sb + (kt % N_STAGE) * ST_BYTES;

        if (kt + 1 < KT)
            asm volatile("cp.async.wait_group 1;" ::: "memory");
        else
            asm volatile("cp.async.wait_group 0;" ::: "memory");
        __syncthreads();

        if constexpr (!AHALF) { if (kt + 2 < KT) loadA(kt + 2); }  // LDG under mma

        #pragma unroll
        for (int kk = 0; kk < 2; kk++) {
            const uint32_t ko = kk * 32;
            uint32_t afh[4][4];
            #pragma unroll
            for (int mt = 0; mt < 4; mt++)
                ldsm4(afh[mt], cur + aOff + mt * (16 * BKP * 2) + ko);
            #pragma unroll
            for (int np = 0; np < 4; np++) {
                uint32_t bfh[4];
                ldsm4(bfh, cur + OFF_B + bOff + np * (16 * BKP * 2) + ko);
                #pragma unroll
                for (int mt = 0; mt < 4; mt++)
                    #pragma unroll
                    for (int j = 0; j < 2; j++)
                        mma16816(acc[mt][np * 2 + j], afh[mt], &bfh[j * 2]);
            }
        }

        if (kt + 2 < KT) {                   // stage (kt+2)%3 freed at iter kt-1
            const uint32_t s2 = sb + ((kt + 2) % N_STAGE) * ST_BYTES;
            if constexpr (AHALF) { cpA(kt + 2, s2); }
            else                 { stsA(s2); }
            cpB(kt + 2, s2);
        }
    }

    // epilogue: H fp16 (half2 per col pair)
    #pragma unroll
    for (int mt = 0; mt < 4; mt++) {
        int r0 = bm + wm + mt * 16 + (lane >> 2);
        int r1 = r0 + 8;
        #pragma unroll
        for (int nt = 0; nt < 8; nt++) {
            int cn = bn + wn + nt * 8 + (lane & 3) * 2;   // even
            if (r0 < M) {
                __half2 hv; hv.x = __float2half_rn(acc[mt][nt][0]);
                            hv.y = __float2half_rn(acc[mt][nt][1]);
                H[(size_t)r0 * 128 + (cn >> 1)] = hv;
            }
            if (r1 < M) {
                __half2 hv; hv.x = __float2half_rn(acc[mt][nt][2]);
                            hv.y = __float2half_rn(acc[mt][nt][3]);
                H[(size_t)r1 * 128 + (cn >> 1)] = hv;
            }
        }
    }
}

// ---------------- CSR aggregation ---------------------------------------------
__device__ __forceinline__ void h2mac(uint32_t u, float w, float& x, float& y) {
    __half2 hh = *(__half2*)&u;
    float2 f = __half22float2(hh);
    x = fmaf(f.x, w, x); y = fmaf(f.y, w, y);
}

// layer 1: a16 = relu(agg(h) + b1), fp16 output (GEMM2 A input, no FUSE needed)
__global__ __launch_bounds__(256) void k_agg_relu(const __half2* __restrict__ h,
                                                  const float* __restrict__ b1,
                                                  __half2* __restrict__ a16) {
    int r = blockIdx.x * 8 + (threadIdx.x >> 5);
    if (r >= N_NODES) return;
    int lane = threadIdx.x & 31;
    float dr = g_dinv[r];
    float w0 = dr * dr;
    const uint4* hp = (const uint4*)h;           // 16B = 8 halves; 32 uint4 per row
    uint4 v = hp[(size_t)r * 32 + lane];
    float acc[8] = {0, 0, 0, 0, 0, 0, 0, 0};
    h2mac(v.x, w0, acc[0], acc[1]); h2mac(v.y, w0, acc[2], acc[3]);
    h2mac(v.z, w0, acc[4], acc[5]); h2mac(v.w, w0, acc[6], acc[7]);
    int beg = g_rowbeg[r], end = beg + g_indeg[r];
    for (int t = beg; t < end; t++) {
        int s = g_csrc[t];
        float w = g_dinv[s] * dr;
        uint4 u = hp[(size_t)s * 32 + lane];
        h2mac(u.x, w, acc[0], acc[1]); h2mac(u.y, w, acc[2], acc[3]);
        h2mac(u.z, w, acc[4], acc[5]); h2mac(u.w, w, acc[6], acc[7]);
    }
    float4 bb0 = *(const float4*)(b1 + lane * 8);
    float4 bb1 = *(const float4*)(b1 + lane * 8 + 4);
    float bv[8] = {bb0.x, bb0.y, bb0.z, bb0.w, bb1.x, bb1.y, bb1.z, bb1.w};
    uint4 o;
    uint32_t* op = (uint32_t*)&o;
    #pragma unroll
    for (int p = 0; p < 4; p++) {
        __half2 hh;
        hh.x = __float2half_rn(fmaxf(acc[2*p]   + bv[2*p],   0.f));
        hh.y = __float2half_rn(fmaxf(acc[2*p+1] + bv[2*p+1], 0.f));
        op[p] = *(uint32_t*)&hh;
    }
    ((uint4*)a16)[(size_t)r * 32 + lane] = o;
}

// layer 2: a = agg(h), fp32 output (pool input)
__global__ __launch_bounds__(256) void k_agg_f32(const __half2* __restrict__ h,
                                                 float* __restrict__ a) {
    int r = blockIdx.x * 8 + (threadIdx.x >> 5);
    if (r >= N_NODES) return;
    int lane = threadIdx.x & 31;
    float dr = g_dinv[r];
    float w0 = dr * dr;
    const uint4* hp = (const uint4*)h;
    uint4 v = hp[(size_t)r * 32 + lane];
    float acc[8] = {0, 0, 0, 0, 0, 0, 0, 0};
    h2mac(v.x, w0, acc[0], acc[1]); h2mac(v.y, w0, acc[2], acc[3]);
    h2mac(v.z, w0, acc[4], acc[5]); h2mac(v.w, w0, acc[6], acc[7]);
    int beg = g_rowbeg[r], end = beg + g_indeg[r];
    for (int t = beg; t < end; t++) {
        int s = g_csrc[t];
        float w = g_dinv[s] * dr;
        uint4 u = hp[(size_t)s * 32 + lane];
        h2mac(u.x, w, acc[0], acc[1]); h2mac(u.y, w, acc[2], acc[3]);
        h2mac(u.z, w, acc[4], acc[5]); h2mac(u.w, w, acc[6], acc[7]);
    }
    float* ar = a + (size_t)r * 256 + lane * 8;
    *(float4*)ar       = make_float4(acc[0], acc[1], acc[2], acc[3]);
    *(float4*)(ar + 4) = make_float4(acc[4], acc[5], acc[6], acc[7]);
}

// ---------------- pooling: batch sorted -> binary search per graph -----------
__global__ void k_pool(const float* __restrict__ a, const float* __restrict__ b2,
                       float* __restrict__ out) {
    int g = blockIdx.x;
    __shared__ int sLo, sHi;
    if (threadIdx.x == 0) {
        int lo = 0, hi = N_NODES;
        while (lo < hi) { int mid = (lo + hi) >> 1; if (g_batch[mid] < g) lo = mid + 1; else hi = mid; }
        sLo = lo;
        hi = N_NODES;
        while (lo < hi) { int mid = (lo + hi) >> 1; if (g_batch[mid] < g + 1) lo = mid + 1; else hi = mid; }
        sHi = lo;
    }
    __syncthreads();
    int c = threadIdx.x;
    float sum = 0.0f;
    for (int v = sLo; v < sHi; v++) sum += a[(size_t)v * 256 + c];
    int cnt = sHi - sLo;
    out[(size_t)g * 256 + c] = (cnt > 0) ? (sum / (float)cnt + b2[c]) : 0.0f;
}

// ---------------- launcher ---------------------------------------------------
extern "C" void kernel_launch(void* const* d_in, const int* in_sizes, int n_in,
                              void* d_out, int out_size) {
    const float* x    = (const float*)d_in[0];
    const float* W1   = (const float*)d_in[1];
    const float* b1   = (const float*)d_in[2];
    const float* W2   = (const float*)d_in[3];
    const float* b2   = (const float*)d_in[4];
    const void*  ei   = d_in[5];
    const void*  bat  = d_in[6];
    float* out = (float*)d_out;

    float *pa;
    __half2 *ph, *pa16;
    __half *pw1, *pw2;
    cudaGetSymbolAddress((void**)&ph, g_h);
    cudaGetSymbolAddress((void**)&pa16, g_a16);
    cudaGetSymbolAddress((void**)&pa, g_a);
    cudaGetSymbolAddress((void**)&pw1, g_w1);
    cudaGetSymbolAddress((void**)&pw2, g_w2);

    cudaFuncSetAttribute(k_gemm_tc<IN_CH, false>,
                         cudaFuncAttributeMaxDynamicSharedMemorySize, SMEM_DYN);
    cudaFuncSetAttribute(k_gemm_tc<HID_CH, true>,
                         cudaFuncAttributeMaxDynamicSharedMemorySize, SMEM_DYN);

    dim3 gemmGrid(2, (N_NODES + 127) / 128);     // N-tile fastest: twins share A in L2

    // launch index 3 = GEMM1 (ncu profiles launch index 3)
    k_detect<<<1, 256>>>((const int*)ei);                                 // 0
    k_wprep<<<((IN_CH + HID_CH) * 256 + 255) / 256, 256>>>(W1, W2);       // 1 (zeros indeg too)
    k_convert_deg<<<(2 * N_EDGES + 255) / 256, 256>>>(ei, bat);           // 2
    k_gemm_tc<IN_CH, false><<<gemmGrid, 128, SMEM_DYN>>>(                 // 3 <- profiled
        x, pw1, ph, N_NODES);
    k_alloc<<<(N_NODES + 255) / 256, 256>>>();                            // 4
    k_fill<<<(N_EDGES + 255) / 256, 256>>>();                             // 5
    k_agg_relu<<<(N_NODES + 7) / 8, 256>>>(ph, b1, pa16);                 // 6
    k_gemm_tc<HID_CH, true><<<gemmGrid, 128, SMEM_DYN>>>(                 // 7
        pa16, pw2, ph, N_NODES);
    k_agg_f32<<<(N_NODES + 7) / 8, 256>>>(ph, pa);                        // 8
    k_pool<<<NUM_GRAPHS, 256>>>(pa, b2, out);                             // 9
}

// round 12
// speedup vs baseline: 1.2165x; 1.2165x over previous
#include <cuda_runtime.h>
#include <cuda_fp16.h>
#include <cstdint>

#define N_NODES   200000
#define N_EDGES   400000
#define IN_CH     768
#define HID_CH    256
#define NUM_GRAPHS 8000

// ---------------- scratch (device globals: no allocations allowed) ----------
__device__ int   g_is64;
__device__ int   g_total;
__device__ int   g_edges[2 * N_EDGES];          // [src(E), dst(E)] as int32
__device__ int   g_batch[N_NODES];
__device__ int   g_indeg[N_NODES];
__device__ int   g_rowbeg[N_NODES];             // CSR range start (arbitrary order)
__device__ int   g_cursor[N_NODES];
__device__ int   g_csrc[N_EDGES];               // CSR-by-dst: src ids
__device__ float g_dinv[N_NODES];               // rsqrt(1 + indeg)
__device__ __half2 g_h[(size_t)N_NODES * 128];  // GEMM output, fp16 (gather-read)
__device__ __half2 g_a16[(size_t)(N_NODES + 128) * 128]; // relu(agg+b1), fp16 (padded tail)
__device__ float g_a[(size_t)N_NODES * 256];    // layer-2 agg output, fp32 (pool input)
__device__ __half g_w1[256 * IN_CH];            // W^T fp16, [n][k] K-major
__device__ __half g_w2[256 * HID_CH];

// ---------------- setup ------------------------------------------------------
__global__ void k_detect(const int* ei32) {
    __shared__ int any;
    if (threadIdx.x == 0) any = 0;
    __syncthreads();
    int idx = threadIdx.x * 3120 + 1;           // max 795601 < 800000 (safe if int32)
    if (ei32[idx] != 0) any = 1;
    __syncthreads();
    if (threadIdx.x == 0) { g_is64 = (any == 0) ? 1 : 0; g_total = 0; }
}

__global__ void k_wprep(const float* __restrict__ W1, const float* __restrict__ W2) {
    int i = blockIdx.x * blockDim.x + threadIdx.x;
    if (i < N_NODES) g_indeg[i] = 0;
    if (i < IN_CH * 256) {
        int k = i / 256, n = i % 256;
        g_w1[(size_t)n * IN_CH + k] = __float2half_rn(W1[i]);
    } else {
        int j = i - IN_CH * 256;
        if (j < HID_CH * 256) {
            int k = j / 256, n = j % 256;
            g_w2[(size_t)n * HID_CH + k] = __float2half_rn(W2[j]);
        }
    }
}

__global__ void k_convert_deg(const void* ei, const void* bat) {
    int i = blockIdx.x * blockDim.x + threadIdx.x;
    bool is64 = (g_is64 != 0);
    if (i < N_NODES) {
        g_batch[i] = is64 ? (int)((const long long*)bat)[i] : ((const int*)bat)[i];
    }
    if (i < 2 * N_EDGES) {
        int v = is64 ? (int)((const long long*)ei)[i] : ((const int*)ei)[i];
        g_edges[i] = v;
        if (i >= N_EDGES) atomicAdd(&g_indeg[v], 1);   // dst half
    }
}

__global__ void k_alloc() {
    int i = blockIdx.x * blockDim.x + threadIdx.x;
    if (i >= N_NODES) return;
    int d = g_indeg[i];
    int beg = atomicAdd(&g_total, d);           // uniform-addr -> REDUX aggregated
    g_rowbeg[i] = beg;
    g_cursor[i] = beg;
    g_dinv[i] = rsqrtf(1.0f + (float)d);
}

__global__ void k_fill() {
    int e = blockIdx.x * blockDim.x + threadIdx.x;
    if (e < N_EDGES) {
        int s = g_edges[e], d = g_edges[N_EDGES + e];
        int pos = atomicAdd(&g_cursor[d], 1);
        g_csrc[pos] = s;
    }
}

// ---------------- GEMM helpers ------------------------------------------------
__device__ __forceinline__ void ldsm4(uint32_t r[4], uint32_t addr) {
    asm volatile("ldmatrix.sync.aligned.m8n8.x4.shared.b16 {%0,%1,%2,%3}, [%4];"
        : "=r"(r[0]), "=r"(r[1]), "=r"(r[2]), "=r"(r[3]) : "r"(addr));
}
__device__ __forceinline__ void mma16816(float c[4], const uint32_t a[4], const uint32_t b[2]) {
    asm volatile(
        "mma.sync.aligned.m16n8k16.row.col.f32.f16.f16.f32 "
        "{%0,%1,%2,%3}, {%4,%5,%6,%7}, {%8,%9}, {%0,%1,%2,%3};"
        : "+f"(c[0]), "+f"(c[1]), "+f"(c[2]), "+f"(c[3])
        : "r"(a[0]), "r"(a[1]), "r"(a[2]), "r"(a[3]), "r"(b[0]), "r"(b[1]));
}
__device__ __forceinline__ void cpasync16(uint32_t dst, const void* src) {
    asm volatile("cp.async.cg.shared.global [%0], [%1], 16;" :: "r"(dst), "l"(src));
}
__device__ __forceinline__ uint32_t smem_u32(const void* p) {
    uint32_t a;
    asm("{ .reg .u64 t; cvta.to.shared.u64 t, %1; cvt.u32.u64 %0, t; }" : "=r"(a) : "l"(p));
    return a;
}

// BM=128, BN=128, BK=32, 256 threads (8 warps: 4M x 2N, warp tile 32x64),
// 3-stage cp.async, 2 CTAs/SM (16 warps/SM — R11 showed this is load-bearing).
// AHALF: A is fp16 (g_a16, padded), loaded via cp.async; else fp32 LDG+convert.
#define BKP 40                       // padded BK row (fp16): 80B stride
#define OFF_B (128 * BKP * 2)        // 10240
#define ST_BYTES (2 * 128 * BKP * 2) // 20480 per stage
#define N_STAGE 3
#define SMEM_DYN (N_STAGE * ST_BYTES) // 61440 (2 CTAs = 123KB <= 228KB)

template<int K, bool AHALF>
__global__ __launch_bounds__(256, 2) void k_gemm_tc(
    const void* __restrict__ Av, const __half* __restrict__ B,
    __half2* __restrict__ H, int M)
{
    extern __shared__ __align__(16) char smem[];
    const uint32_t sb = smem_u32(smem);

    const int tid  = threadIdx.x;
    const int lane = tid & 31;
    const int wid  = tid >> 5;
    const int bn   = blockIdx.x * 128;
    const int bm   = blockIdx.y * 128;
    const int wm   = (wid & 3) * 32;
    const int wn   = (wid >> 2) * 64;

    const int gRow  = tid >> 1;
    const int half_ = tid & 1;
    const bool aValid = (bm + gRow) < M;
    const float*  Apf = (const float*) Av + (size_t)(bm + gRow) * K + half_ * 16;
    const __half* Aph = (const __half*)Av + (size_t)(bm + gRow) * K + half_ * 16;
    const __half* Bp  = B + (size_t)(bn + gRow) * K + half_ * 16;
    const uint32_t stsOff = (uint32_t)gRow * (BKP * 2) + half_ * 32;

    const uint32_t aOff = (uint32_t)(wm + (lane & 15)) * (BKP * 2) + ((lane >> 4) << 4);
    const uint32_t bOff = (uint32_t)(wn + (lane & 7) + ((lane >> 4) & 1) * 8) * (BKP * 2)
                        + (((lane >> 3) & 1) << 4);

    float acc[2][8][4];
    #pragma unroll
    for (int mt = 0; mt < 2; mt++)
        #pragma unroll
        for (int nt = 0; nt < 8; nt++)
            #pragma unroll
            for (int j = 0; j < 4; j++) acc[mt][nt][j] = 0.0f;

    constexpr int KT = K / 32;

    float4 aReg[4];                        // !AHALF path only
    auto loadA = [&](int kt) {
        #pragma unroll
        for (int i = 0; i < 4; i++)
            aReg[i] = aValid ? *(const float4*)(Apf + kt * 32 + 4 * i)
                             : make_float4(0.f, 0.f, 0.f, 0.f);
    };
    auto stsA = [&](uint32_t stage) {
        uint32_t hw[8];
        #pragma unroll
        for (int i = 0; i < 4; i++) {
            float4 v = aReg[i];
            __half2 h0; h0.x = __float2half_rn(v.x); h0.y = __float2half_rn(v.y);
            __half2 h1; h1.x = __float2half_rn(v.z); h1.y = __float2half_rn(v.w);
            hw[2 * i]     = *(uint32_t*)&h0;
            hw[2 * i + 1] = *(uint32_t*)&h1;
        }
        uint32_t d = stage + stsOff;
        asm volatile("st.shared.v4.b32 [%0], {%1,%2,%3,%4};"
                     :: "r"(d), "r"(hw[0]), "r"(hw[1]), "r"(hw[2]), "r"(hw[3]) : "memory");
        asm volatile("st.shared.v4.b32 [%0], {%1,%2,%3,%4};"
                     :: "r"(d + 16), "r"(hw[4]), "r"(hw[5]), "r"(hw[6]), "r"(hw[7]) : "memory");
    };
    auto cpA = [&](int kt, uint32_t stage) {   // AHALF: padded global, no guard
        cpasync16(stage + stsOff,      Aph + kt * 32);
        cpasync16(stage + stsOff + 16, Aph + kt * 32 + 8);
    };
    auto cpB = [&](int kt, uint32_t stage) {   // commits the stage's async group
        cpasync16(stage + OFF_B + stsOff,      Bp + kt * 32);
        cpasync16(stage + OFF_B + stsOff + 16, Bp + kt * 32 + 8);
        asm volatile("cp.async.commit_group;" ::: "memory");
    };
    auto fillStage = [&](int kt, uint32_t stage) {
        if constexpr (AHALF) { cpA(kt, stage); }
        else                 { loadA(kt); stsA(stage); }
        cpB(kt, stage);
    };

    // prologue: stages 0 and 1
    fillStage(0, sb);
    fillStage(1, sb + ST_BYTES);

    for (int kt = 0; kt < KT; kt++) {
        const uint32_t cur = sb + (kt % N_STAGE) * ST_BYTES;

        if (kt + 1 < KT)
            asm volatile("cp.async.wait_group 1;" ::: "memory");
        else
            asm volatile("cp.async.wait_group 0;" ::: "memory");
        __syncthreads();

        if constexpr (!AHALF) { if (kt + 2 < KT) loadA(kt + 2); }  // LDG under mma

        #pragma unroll
        for (int kk = 0; kk < 2; kk++) {
            const uint32_t ko = kk * 32;
            uint32_t afh[2][4];
            #pragma unroll
            for (int mt = 0; mt < 2; mt++)
                ldsm4(afh[mt], cur + aOff + mt * (16 * BKP * 2) + ko);
            #pragma unroll
            for (int np = 0; np < 4; np++) {
                uint32_t bfh[4];
                ldsm4(bfh, cur + OFF_B + bOff + np * (16 * BKP * 2) + ko);
                #pragma unroll
                for (int mt = 0; mt < 2; mt++)
                    #pragma unroll
                    for (int j = 0; j < 2; j++)
                        mma16816(acc[mt][np * 2 + j], afh[mt], &bfh[j * 2]);
            }
        }

        if (kt + 2 < KT) {                   // stage (kt+2)%3 freed at iter kt-1
            const uint32_t s2 = sb + ((kt + 2) % N_STAGE) * ST_BYTES;
            if constexpr (AHALF) { cpA(kt + 2, s2); }
            else                 { stsA(s2); }
            cpB(kt + 2, s2);
        }
    }

    // epilogue: H fp16 (half2 per col pair)
    #pragma unroll
    for (int mt = 0; mt < 2; mt++) {
        int r0 = bm + wm + mt * 16 + (lane >> 2);
        int r1 = r0 + 8;
        #pragma unroll
        for (int nt = 0; nt < 8; nt++) {
            int cn = bn + wn + nt * 8 + (lane & 3) * 2;   // even
            if (r0 < M) {
                __half2 hv; hv.x = __float2half_rn(acc[mt][nt][0]);
                            hv.y = __float2half_rn(acc[mt][nt][1]);
                H[(size_t)r0 * 128 + (cn >> 1)] = hv;
            }
            if (r1 < M) {
                __half2 hv; hv.x = __float2half_rn(acc[mt][nt][2]);
                            hv.y = __float2half_rn(acc[mt][nt][3]);
                H[(size_t)r1 * 128 + (cn >> 1)] = hv;
            }
        }
    }
}

// ---------------- CSR aggregation ---------------------------------------------
__device__ __forceinline__ void h2mac(uint32_t u, float w, float& x, float& y) {
    __half2 hh = *(__half2*)&u;
    float2 f = __half22float2(hh);
    x = fmaf(f.x, w, x); y = fmaf(f.y, w, y);
}

// layer 1: a16 = relu(agg(h) + b1), fp16 output (GEMM2 A input)
__global__ __launch_bounds__(256) void k_agg_relu(const __half2* __restrict__ h,
                                                  const float* __restrict__ b1,
                                                  __half2* __restrict__ a16) {
    int r = blockIdx.x * 8 + (threadIdx.x >> 5);
    if (r >= N_NODES) return;
    int lane = threadIdx.x & 31;
    float dr = g_dinv[r];
    float w0 = dr * dr;
    const uint4* hp = (const uint4*)h;           // 16B = 8 halves; 32 uint4 per row
    uint4 v = hp[(size_t)r * 32 + lane];
    float acc[8] = {0, 0, 0, 0, 0, 0, 0, 0};
    h2mac(v.x, w0, acc[0], acc[1]); h2mac(v.y, w0, acc[2], acc[3]);
    h2mac(v.z, w0, acc[4], acc[5]); h2mac(v.w, w0, acc[6], acc[7]);
    int beg = g_rowbeg[r], end = beg + g_indeg[r];
    for (int t = beg; t < end; t++) {
        int s = g_csrc[t];
        float w = g_dinv[s] * dr;
        uint4 u = hp[(size_t)s * 32 + lane];
        h2mac(u.x, w, acc[0], acc[1]); h2mac(u.y, w, acc[2], acc[3]);
        h2mac(u.z, w, acc[4], acc[5]); h2mac(u.w, w, acc[6], acc[7]);
    }
    float4 bb0 = *(const float4*)(b1 + lane * 8);
    float4 bb1 = *(const float4*)(b1 + lane * 8 + 4);
    float bv[8] = {bb0.x, bb0.y, bb0.z, bb0.w, bb1.x, bb1.y, bb1.z, bb1.w};
    uint4 o;
    uint32_t* op = (uint32_t*)&o;
    #pragma unroll
    for (int p = 0; p < 4; p++) {
        __half2 hh;
        hh.x = __float2half_rn(fmaxf(acc[2*p]   + bv[2*p],   0.f));
        hh.y = __float2half_rn(fmaxf(acc[2*p+1] + bv[2*p+1], 0.f));
        op[p] = *(uint32_t*)&hh;
    }
    ((uint4*)a16)[(size_t)r * 32 + lane] = o;
}

// layer 2: a = agg(h), fp32 output (pool input)
__global__ __launch_bounds__(256) void k_agg_f32(const __half2* __restrict__ h,
                                                 float* __restrict__ a) {
    int r = blockIdx.x * 8 + (threadIdx.x >> 5);
    if (r >= N_NODES) return;
    int lane = threadIdx.x & 31;
    float dr = g_dinv[r];
    float w0 = dr * dr;
    const uint4* hp = (const uint4*)h;
    uint4 v = hp[(size_t)r * 32 + lane];
    float acc[8] = {0, 0, 0, 0, 0, 0, 0, 0};
    h2mac(v.x, w0, acc[0], acc[1]); h2mac(v.y, w0, acc[2], acc[3]);
    h2mac(v.z, w0, acc[4], acc[5]); h2mac(v.w, w0, acc[6], acc[7]);
    int beg = g_rowbeg[r], end = beg + g_indeg[r];
    for (int t = beg; t < end; t++) {
        int s = g_csrc[t];
        float w = g_dinv[s] * dr;
        uint4 u = hp[(size_t)s * 32 + lane];
        h2mac(u.x, w, acc[0], acc[1]); h2mac(u.y, w, acc[2], acc[3]);
        h2mac(u.z, w, acc[4], acc[5]); h2mac(u.w, w, acc[6], acc[7]);
    }
    float* ar = a + (size_t)r * 256 + lane * 8;
    *(float4*)ar       = make_float4(acc[0], acc[1], acc[2], acc[3]);
    *(float4*)(ar + 4) = make_float4(acc[4], acc[5], acc[6], acc[7]);
}

// ---------------- pooling: batch sorted -> binary search per graph -----------
__global__ void k_pool(const float* __restrict__ a, const float* __restrict__ b2,
                       float* __restrict__ out) {
    int g = blockIdx.x;
    __shared__ int sLo, sHi;
    if (threadIdx.x == 0) {
        int lo = 0, hi = N_NODES;
        while (lo < hi) { int mid = (lo + hi) >> 1; if (g_batch[mid] < g) lo = mid + 1; else hi = mid; }
        sLo = lo;
        hi = N_NODES;
        while (lo < hi) { int mid = (lo + hi) >> 1; if (g_batch[mid] < g + 1) lo = mid + 1; else hi = mid; }
        sHi = lo;
    }
    __syncthreads();
    int c = threadIdx.x;
    float sum = 0.0f;
    for (int v = sLo; v < sHi; v++) sum += a[(size_t)v * 256 + c];
    int cnt = sHi - sLo;
    out[(size_t)g * 256 + c] = (cnt > 0) ? (sum / (float)cnt + b2[c]) : 0.0f;
}

// ---------------- launcher ---------------------------------------------------
extern "C" void kernel_launch(void* const* d_in, const int* in_sizes, int n_in,
                              void* d_out, int out_size) {
    const float* x    = (const float*)d_in[0];
    const float* W1   = (const float*)d_in[1];
    const float* b1   = (const float*)d_in[2];
    const float* W2   = (const float*)d_in[3];
    const float* b2   = (const float*)d_in[4];
    const void*  ei   = d_in[5];
    const void*  bat  = d_in[6];
    float* out = (float*)d_out;

    float *pa;
    __half2 *ph, *pa16;
    __half *pw1, *pw2;
    cudaGetSymbolAddress((void**)&ph, g_h);
    cudaGetSymbolAddress((void**)&pa16, g_a16);
    cudaGetSymbolAddress((void**)&pa, g_a);
    cudaGetSymbolAddress((void**)&pw1, g_w1);
    cudaGetSymbolAddress((void**)&pw2, g_w2);

    cudaFuncSetAttribute(k_gemm_tc<IN_CH, false>,
                         cudaFuncAttributeMaxDynamicSharedMemorySize, SMEM_DYN);
    cudaFuncSetAttribute(k_gemm_tc<HID_CH, true>,
                         cudaFuncAttributeMaxDynamicSharedMemorySize, SMEM_DYN);

    dim3 gemmGrid(2, (N_NODES + 127) / 128);     // N-tile fastest: twins share A in L2

    // launch index 3 = GEMM1 (ncu profiles launch index 3)
    k_detect<<<1, 256>>>((const int*)ei);                                 // 0
    k_wprep<<<((IN_CH + HID_CH) * 256 + 255) / 256, 256>>>(W1, W2);       // 1 (zeros indeg too)
    k_convert_deg<<<(2 * N_EDGES + 255) / 256, 256>>>(ei, bat);           // 2
    k_gemm_tc<IN_CH, false><<<gemmGrid, 256, SMEM_DYN>>>(                 // 3 <- profiled
        x, pw1, ph, N_NODES);
    k_alloc<<<(N_NODES + 255) / 256, 256>>>();                            // 4
    k_fill<<<(N_EDGES + 255) / 256, 256>>>();                             // 5
    k_agg_relu<<<(N_NODES + 7) / 8, 256>>>(ph, b1, pa16);                 // 6
    k_gemm_tc<HID_CH, true><<<gemmGrid, 256, SMEM_DYN>>>(                 // 7
        pa16, pw2, ph, N_NODES);
    k_agg_f32<<<(N_NODES + 7) / 8, 256>>>(ph, pa);                        // 8
    k_pool<<<NUM_GRAPHS, 256>>>(pa, b2, out);                             // 9
}

// round 13
// speedup vs baseline: 1.3058x; 1.0734x over previous
#include <cuda_runtime.h>
#include <cuda_fp16.h>
#include <cstdint>

#define N_NODES   200000
#define N_EDGES   400000
#define IN_CH     768
#define HID_CH    256
#define NUM_GRAPHS 8000

// ---------------- scratch (device globals: no allocations allowed) ----------
__device__ int   g_is64;
__device__ int   g_total;
__device__ int   g_edges[2 * N_EDGES];          // [src(E), dst(E)] as int32
__device__ int   g_batch[N_NODES];
__device__ int   g_indeg[N_NODES];
__device__ int   g_rowbeg[N_NODES];             // CSR range start (arbitrary order)
__device__ int   g_cursor[N_NODES];
__device__ int   g_csrc[N_EDGES];               // CSR-by-dst: src ids
__device__ float g_dinv[N_NODES];               // rsqrt(1 + indeg)
__device__ __half2 g_h[(size_t)N_NODES * 128];  // GEMM output, fp16 (gather-read)
__device__ __half2 g_a16[(size_t)(N_NODES + 128) * 128]; // relu(agg+b1), fp16 (padded tail)
__device__ __half g_w1[256 * IN_CH];            // W^T fp16, [n][k] K-major
__device__ __half g_w2[256 * HID_CH];

// ---------------- setup ------------------------------------------------------
__global__ void k_detect(const int* ei32) {
    __shared__ int any;
    if (threadIdx.x == 0) any = 0;
    __syncthreads();
    int idx = threadIdx.x * 3120 + 1;           // max 795601 < 800000 (safe if int32)
    if (ei32[idx] != 0) any = 1;
    __syncthreads();
    if (threadIdx.x == 0) { g_is64 = (any == 0) ? 1 : 0; g_total = 0; }
}

__global__ void k_wprep(const float* __restrict__ W1, const float* __restrict__ W2) {
    int i = blockIdx.x * blockDim.x + threadIdx.x;
    if (i < N_NODES) g_indeg[i] = 0;
    if (i < IN_CH * 256) {
        int k = i / 256, n = i % 256;
        g_w1[(size_t)n * IN_CH + k] = __float2half_rn(W1[i]);
    } else {
        int j = i - IN_CH * 256;
        if (j < HID_CH * 256) {
            int k = j / 256, n = j % 256;
            g_w2[(size_t)n * HID_CH + k] = __float2half_rn(W2[j]);
        }
    }
}

__global__ void k_convert_deg(const void* ei, const void* bat) {
    int i = blockIdx.x * blockDim.x + threadIdx.x;
    bool is64 = (g_is64 != 0);
    if (i < N_NODES) {
        g_batch[i] = is64 ? (int)((const long long*)bat)[i] : ((const int*)bat)[i];
    }
    if (i < 2 * N_EDGES) {
        int v = is64 ? (int)((const long long*)ei)[i] : ((const int*)ei)[i];
        g_edges[i] = v;
        if (i >= N_EDGES) atomicAdd(&g_indeg[v], 1);   // dst half
    }
}

__global__ void k_alloc() {
    int i = blockIdx.x * blockDim.x + threadIdx.x;
    if (i >= N_NODES) return;
    int d = g_indeg[i];
    int beg = atomicAdd(&g_total, d);           // uniform-addr -> REDUX aggregated
    g_rowbeg[i] = beg;
    g_cursor[i] = beg;
    g_dinv[i] = rsqrtf(1.0f + (float)d);
}

__global__ void k_fill() {
    int e = blockIdx.x * blockDim.x + threadIdx.x;
    if (e < N_EDGES) {
        int s = g_edges[e], d = g_edges[N_EDGES + e];
        int pos = atomicAdd(&g_cursor[d], 1);
        g_csrc[pos] = s;
    }
}

// ---------------- GEMM helpers ------------------------------------------------
__device__ __forceinline__ void ldsm4(uint32_t r[4], uint32_t addr) {
    asm volatile("ldmatrix.sync.aligned.m8n8.x4.shared.b16 {%0,%1,%2,%3}, [%4];"
        : "=r"(r[0]), "=r"(r[1]), "=r"(r[2]), "=r"(r[3]) : "r"(addr));
}
__device__ __forceinline__ void mma16816(float c[4], const uint32_t a[4], const uint32_t b[2]) {
    asm volatile(
        "mma.sync.aligned.m16n8k16.row.col.f32.f16.f16.f32 "
        "{%0,%1,%2,%3}, {%4,%5,%6,%7}, {%8,%9}, {%0,%1,%2,%3};"
        : "+f"(c[0]), "+f"(c[1]), "+f"(c[2]), "+f"(c[3])
        : "r"(a[0]), "r"(a[1]), "r"(a[2]), "r"(a[3]), "r"(b[0]), "r"(b[1]));
}
__device__ __forceinline__ void cpasync16(uint32_t dst, const void* src) {
    asm volatile("cp.async.cg.shared.global [%0], [%1], 16;" :: "r"(dst), "l"(src));
}
__device__ __forceinline__ uint32_t smem_u32(const void* p) {
    uint32_t a;
    asm("{ .reg .u64 t; cvta.to.shared.u64 t, %1; cvt.u32.u64 %0, t; }" : "=r"(a) : "l"(p));
    return a;
}

// BM=128, BN=128, BK=32, 256 threads (8 warps: 4M x 2N, warp tile 32x64),
// 3-stage cp.async, 2 CTAs/SM (16 warps/SM — R11 showed this is load-bearing).
// AHALF: A is fp16 (g_a16, padded), loaded via cp.async; else fp32 LDG+convert.
#define BKP 40                       // padded BK row (fp16): 80B stride
#define OFF_B (128 * BKP * 2)        // 10240
#define ST_BYTES (2 * 128 * BKP * 2) // 20480 per stage
#define N_STAGE 3
#define SMEM_DYN (N_STAGE * ST_BYTES) // 61440 (2 CTAs = 123KB <= 228KB)

template<int K, bool AHALF>
__global__ __launch_bounds__(256, 2) void k_gemm_tc(
    const void* __restrict__ Av, const __half* __restrict__ B,
    __half2* __restrict__ H, int M)
{
    extern __shared__ __align__(16) char smem[];
    const uint32_t sb = smem_u32(smem);

    const int tid  = threadIdx.x;
    const int lane = tid & 31;
    const int wid  = tid >> 5;
    const int bn   = blockIdx.x * 128;
    const int bm   = blockIdx.y * 128;
    const int wm   = (wid & 3) * 32;
    const int wn   = (wid >> 2) * 64;

    const int gRow  = tid >> 1;
    const int half_ = tid & 1;
    const bool aValid = (bm + gRow) < M;
    const float*  Apf = (const float*) Av + (size_t)(bm + gRow) * K + half_ * 16;
    const __half* Aph = (const __half*)Av + (size_t)(bm + gRow) * K + half_ * 16;
    const __half* Bp  = B + (size_t)(bn + gRow) * K + half_ * 16;
    const uint32_t stsOff = (uint32_t)gRow * (BKP * 2) + half_ * 32;

    const uint32_t aOff = (uint32_t)(wm + (lane & 15)) * (BKP * 2) + ((lane >> 4) << 4);
    const uint32_t bOff = (uint32_t)(wn + (lane & 7) + ((lane >> 4) & 1) * 8) * (BKP * 2)
                        + (((lane >> 3) & 1) << 4);

    float acc[2][8][4];
    #pragma unroll
    for (int mt = 0; mt < 2; mt++)
        #pragma unroll
        for (int nt = 0; nt < 8; nt++)
            #pragma unroll
            for (int j = 0; j < 4; j++) acc[mt][nt][j] = 0.0f;

    constexpr int KT = K / 32;

    float4 aReg[4];                        // !AHALF path only
    auto loadA = [&](int kt) {
        #pragma unroll
        for (int i = 0; i < 4; i++)
            aReg[i] = aValid ? *(const float4*)(Apf + kt * 32 + 4 * i)
                             : make_float4(0.f, 0.f, 0.f, 0.f);
    };
    auto stsA = [&](uint32_t stage) {
        uint32_t hw[8];
        #pragma unroll
        for (int i = 0; i < 4; i++) {
            float4 v = aReg[i];
            __half2 h0; h0.x = __float2half_rn(v.x); h0.y = __float2half_rn(v.y);
            __half2 h1; h1.x = __float2half_rn(v.z); h1.y = __float2half_rn(v.w);
            hw[2 * i]     = *(uint32_t*)&h0;
            hw[2 * i + 1] = *(uint32_t*)&h1;
        }
        uint32_t d = stage + stsOff;
        asm volatile("st.shared.v4.b32 [%0], {%1,%2,%3,%4};"
                     :: "r"(d), "r"(hw[0]), "r"(hw[1]), "r"(hw[2]), "r"(hw[3]) : "memory");
        asm volatile("st.shared.v4.b32 [%0], {%1,%2,%3,%4};"
                     :: "r"(d + 16), "r"(hw[4]), "r"(hw[5]), "r"(hw[6]), "r"(hw[7]) : "memory");
    };
    auto cpA = [&](int kt, uint32_t stage) {   // AHALF: padded global, no guard
        cpasync16(stage + stsOff,      Aph + kt * 32);
        cpasync16(stage + stsOff + 16, Aph + kt * 32 + 8);
    };
    auto cpB = [&](int kt, uint32_t stage) {   // commits the stage's async group
        cpasync16(stage + OFF_B + stsOff,      Bp + kt * 32);
        cpasync16(stage + OFF_B + stsOff + 16, Bp + kt * 32 + 8);
        asm volatile("cp.async.commit_group;" ::: "memory");
    };
    auto fillStage = [&](int kt, uint32_t stage) {
        if constexpr (AHALF) { cpA(kt, stage); }
        else                 { loadA(kt); stsA(stage); }
        cpB(kt, stage);
    };

    // prologue: stages 0 and 1
    fillStage(0, sb);
    fillStage(1, sb + ST_BYTES);

    for (int kt = 0; kt < KT; kt++) {
        const uint32_t cur = sb + (kt % N_STAGE) * ST_BYTES;

        if (kt + 1 < KT)
            asm volatile("cp.async.wait_group 1;" ::: "memory");
        else
            asm volatile("cp.async.wait_group 0;" ::: "memory");
        __syncthreads();

        if constexpr (!AHALF) { if (kt + 2 < KT) loadA(kt + 2); }  // LDG under mma

        #pragma unroll
        for (int kk = 0; kk < 2; kk++) {
            const uint32_t ko = kk * 32;
            uint32_t afh[2][4];
            #pragma unroll
            for (int mt = 0; mt < 2; mt++)
                ldsm4(afh[mt], cur + aOff + mt * (16 * BKP * 2) + ko);
            #pragma unroll
            for (int np = 0; np < 4; np++) {
                uint32_t bfh[4];
                ldsm4(bfh, cur + OFF_B + bOff + np * (16 * BKP * 2) + ko);
                #pragma unroll
                for (int mt = 0; mt < 2; mt++)
                    #pragma unroll
                    for (int j = 0; j < 2; j++)
                        mma16816(acc[mt][np * 2 + j], afh[mt], &bfh[j * 2]);
            }
        }

        if (kt + 2 < KT) {                   // stage (kt+2)%3 freed at iter kt-1
            const uint32_t s2 = sb + ((kt + 2) % N_STAGE) * ST_BYTES;
            if constexpr (AHALF) { cpA(kt + 2, s2); }
            else                 { stsA(s2); }
            cpB(kt + 2, s2);
        }
    }

    // epilogue: H fp16 (half2 per col pair)
    #pragma unroll
    for (int mt = 0; mt < 2; mt++) {
        int r0 = bm + wm + mt * 16 + (lane >> 2);
        int r1 = r0 + 8;
        #pragma unroll
        for (int nt = 0; nt < 8; nt++) {
            int cn = bn + wn + nt * 8 + (lane & 3) * 2;   // even
            if (r0 < M) {
                __half2 hv; hv.x = __float2half_rn(acc[mt][nt][0]);
                            hv.y = __float2half_rn(acc[mt][nt][1]);
                H[(size_t)r0 * 128 + (cn >> 1)] = hv;
            }
            if (r1 < M) {
                __half2 hv; hv.x = __float2half_rn(acc[mt][nt][2]);
                            hv.y = __float2half_rn(acc[mt][nt][3]);
                H[(size_t)r1 * 128 + (cn >> 1)] = hv;
            }
        }
    }
}

// ---------------- CSR aggregation ---------------------------------------------
__device__ __forceinline__ void h2mac(uint32_t u, float w, float& x, float& y) {
    __half2 hh = *(__half2*)&u;
    float2 f = __half22float2(hh);
    x = fmaf(f.x, w, x); y = fmaf(f.y, w, y);
}

// layer 1: a16 = relu(agg(h) + b1), fp16 output (GEMM2 A input)
__global__ __launch_bounds__(256) void k_agg_relu(const __half2* __restrict__ h,
                                                  const float* __restrict__ b1,
                                                  __half2* __restrict__ a16) {
    int r = blockIdx.x * 8 + (threadIdx.x >> 5);
    if (r >= N_NODES) return;
    int lane = threadIdx.x & 31;
    float dr = g_dinv[r];
    float w0 = dr * dr;
    const uint4* hp = (const uint4*)h;           // 16B = 8 halves; 32 uint4 per row
    uint4 v = hp[(size_t)r * 32 + lane];
    float acc[8] = {0, 0, 0, 0, 0, 0, 0, 0};
    h2mac(v.x, w0, acc[0], acc[1]); h2mac(v.y, w0, acc[2], acc[3]);
    h2mac(v.z, w0, acc[4], acc[5]); h2mac(v.w, w0, acc[6], acc[7]);
    int beg = g_rowbeg[r], end = beg + g_indeg[r];
    for (int t = beg; t < end; t++) {
        int s = g_csrc[t];
        float w = g_dinv[s] * dr;
        uint4 u = hp[(size_t)s * 32 + lane];
        h2mac(u.x, w, acc[0], acc[1]); h2mac(u.y, w, acc[2], acc[3]);
        h2mac(u.z, w, acc[4], acc[5]); h2mac(u.w, w, acc[6], acc[7]);
    }
    float4 bb0 = *(const float4*)(b1 + lane * 8);
    float4 bb1 = *(const float4*)(b1 + lane * 8 + 4);
    float bv[8] = {bb0.x, bb0.y, bb0.z, bb0.w, bb1.x, bb1.y, bb1.z, bb1.w};
    uint4 o;
    uint32_t* op = (uint32_t*)&o;
    #pragma unroll
    for (int p = 0; p < 4; p++) {
        __half2 hh;
        hh.x = __float2half_rn(fmaxf(acc[2*p]   + bv[2*p],   0.f));
        hh.y = __float2half_rn(fmaxf(acc[2*p+1] + bv[2*p+1], 0.f));
        op[p] = *(uint32_t*)&hh;
    }
    ((uint4*)a16)[(size_t)r * 32 + lane] = o;
}

// ---------------- fused layer-2 aggregation + mean pool -----------------------
// Block per graph (batch sorted -> contiguous row range). 8 warps; warp w
// aggregates rows lo+w, lo+w+8, ... directly from fp16 h (same math as the
// old k_agg_f32), accumulating the per-graph column sums in registers; then
// an smem block-reduce across warps; out = sum/cnt + b2 (cnt=0 -> exact 0).
__global__ __launch_bounds__(256) void k_pool_agg(const __half2* __restrict__ h,
                                                  const float* __restrict__ b2,
                                                  float* __restrict__ out) {
    int g = blockIdx.x;
    __shared__ int sLo, sHi;
    __shared__ float red[8][256];
    if (threadIdx.x == 0) {
        int lo = 0, hi = N_NODES;
        while (lo < hi) { int mid = (lo + hi) >> 1; if (g_batch[mid] < g) lo = mid + 1; else hi = mid; }
        sLo = lo;
        hi = N_NODES;
        while (lo < hi) { int mid = (lo + hi) >> 1; if (g_batch[mid] < g + 1) lo = mid + 1; else hi = mid; }
        sHi = lo;
    }
    __syncthreads();
    const int wid  = threadIdx.x >> 5;
    const int lane = threadIdx.x & 31;
    const uint4* hp = (const uint4*)h;

    float acc[8] = {0, 0, 0, 0, 0, 0, 0, 0};
    for (int r = sLo + wid; r < sHi; r += 8) {
        float dr = g_dinv[r];
        float w0 = dr * dr;
        uint4 v = hp[(size_t)r * 32 + lane];
        h2mac(v.x, w0, acc[0], acc[1]); h2mac(v.y, w0, acc[2], acc[3]);
        h2mac(v.z, w0, acc[4], acc[5]); h2mac(v.w, w0, acc[6], acc[7]);
        int beg = g_rowbeg[r], end = beg + g_indeg[r];
        for (int t = beg; t < end; t++) {
            int s = g_csrc[t];
            float w = g_dinv[s] * dr;
            uint4 u = hp[(size_t)s * 32 + lane];
            h2mac(u.x, w, acc[0], acc[1]); h2mac(u.y, w, acc[2], acc[3]);
            h2mac(u.z, w, acc[4], acc[5]); h2mac(u.w, w, acc[6], acc[7]);
        }
    }
    #pragma unroll
    for (int p = 0; p < 8; p++) red[wid][lane * 8 + p] = acc[p];
    __syncthreads();

    int c = threadIdx.x;                // one thread per output column
    int cnt = sHi - sLo;
    float sum = red[0][c] + red[1][c] + red[2][c] + red[3][c]
              + red[4][c] + red[5][c] + red[6][c] + red[7][c];
    out[(size_t)g * 256 + c] = (cnt > 0) ? (sum / (float)cnt + b2[c]) : 0.0f;
}

// ---------------- launcher ---------------------------------------------------
extern "C" void kernel_launch(void* const* d_in, const int* in_sizes, int n_in,
                              void* d_out, int out_size) {
    const float* x    = (const float*)d_in[0];
    const float* W1   = (const float*)d_in[1];
    const float* b1   = (const float*)d_in[2];
    const float* W2   = (const float*)d_in[3];
    const float* b2   = (const float*)d_in[4];
    const void*  ei   = d_in[5];
    const void*  bat  = d_in[6];
    float* out = (float*)d_out;

    __half2 *ph, *pa16;
    __half *pw1, *pw2;
    cudaGetSymbolAddress((void**)&ph, g_h);
    cudaGetSymbolAddress((void**)&pa16, g_a16);
    cudaGetSymbolAddress((void**)&pw1, g_w1);
    cudaGetSymbolAddress((void**)&pw2, g_w2);

    cudaFuncSetAttribute(k_gemm_tc<IN_CH, false>,
                         cudaFuncAttributeMaxDynamicSharedMemorySize, SMEM_DYN);
    cudaFuncSetAttribute(k_gemm_tc<HID_CH, true>,
                         cudaFuncAttributeMaxDynamicSharedMemorySize, SMEM_DYN);

    dim3 gemmGrid(2, (N_NODES + 127) / 128);     // N-tile fastest: twins share A in L2

    // launch index 3 = GEMM1 (ncu profiles launch index 3)
    k_detect<<<1, 256>>>((const int*)ei);                                 // 0
    k_wprep<<<((IN_CH + HID_CH) * 256 + 255) / 256, 256>>>(W1, W2);       // 1 (zeros indeg too)
    k_convert_deg<<<(2 * N_EDGES + 255) / 256, 256>>>(ei, bat);           // 2
    k_gemm_tc<IN_CH, false><<<gemmGrid, 256, SMEM_DYN>>>(                 // 3 <- profiled
        x, pw1, ph, N_NODES);
    k_alloc<<<(N_NODES + 255) / 256, 256>>>();                            // 4
    k_fill<<<(N_EDGES + 255) / 256, 256>>>();                             // 5
    k_agg_relu<<<(N_NODES + 7) / 8, 256>>>(ph, b1, pa16);                 // 6
    k_gemm_tc<HID_CH, true><<<gemmGrid, 256, SMEM_DYN>>>(                 // 7
        pa16, pw2, ph, N_NODES);
    k_pool_agg<<<NUM_GRAPHS, 256>>>(ph, b2, out);                         // 8 (fused agg+pool)
}